// round 1
// baseline (speedup 1.0000x reference)
#include <cuda_runtime.h>
#include <math.h>

#define B_   2
#define S_   2048
#define D_   4096
#define H_   32
#define HK_  8
#define HD_  128
#define M_   (B_ * S_)          // 4096 total tokens
#define KVD_ (HK_ * HD_)        // 1024

// ---------------- scratch (device globals; no allocation allowed) ----------------
__device__ float g_q[(size_t)M_ * D_];        // 4096 x 4096  (67 MB)
__device__ float g_k[(size_t)M_ * KVD_];      // 4096 x 1024
__device__ float g_v[(size_t)M_ * KVD_];      // 4096 x 1024
__device__ float g_attn[(size_t)M_ * D_];     // 4096 x 4096

// =====================================================================
// SGEMM: C[M,N] = A[M,K] * B[N,K]^T  (row-major, M,N mult of 128, K mult of 8)
// 128x128 tile, TK=8, 256 threads, 8x8 per thread.
// =====================================================================
__global__ void __launch_bounds__(256) sgemm_nt(const float* __restrict__ A,
                                                const float* __restrict__ Bm,
                                                float* __restrict__ C,
                                                int M, int N, int K)
{
    __shared__ float As[8][132];
    __shared__ float Bs[8][132];

    const int tid = threadIdx.x;
    const int tx = tid & 15;
    const int ty = tid >> 4;
    const int m0 = blockIdx.y << 7;
    const int n0 = blockIdx.x << 7;

    const int lr = tid >> 1;          // 0..127 : row within tile
    const int lc = (tid & 1) << 2;    // 0 or 4 : starting k within chunk

    const float* ap = A  + (size_t)(m0 + lr) * K + lc;
    const float* bp = Bm + (size_t)(n0 + lr) * K + lc;

    float acc[8][8];
#pragma unroll
    for (int i = 0; i < 8; i++)
#pragma unroll
        for (int j = 0; j < 8; j++) acc[i][j] = 0.0f;

    for (int kb = 0; kb < K; kb += 8) {
        float4 av = *(const float4*)(ap + kb);
        float4 bv = *(const float4*)(bp + kb);
        __syncthreads();
        As[lc + 0][lr] = av.x; As[lc + 1][lr] = av.y;
        As[lc + 2][lr] = av.z; As[lc + 3][lr] = av.w;
        Bs[lc + 0][lr] = bv.x; Bs[lc + 1][lr] = bv.y;
        Bs[lc + 2][lr] = bv.z; Bs[lc + 3][lr] = bv.w;
        __syncthreads();
#pragma unroll
        for (int kk = 0; kk < 8; kk++) {
            float a[8], b[8];
            *(float4*)&a[0] = *(const float4*)&As[kk][ty * 4];
            *(float4*)&a[4] = *(const float4*)&As[kk][64 + ty * 4];
            *(float4*)&b[0] = *(const float4*)&Bs[kk][tx * 4];
            *(float4*)&b[4] = *(const float4*)&Bs[kk][64 + tx * 4];
#pragma unroll
            for (int i = 0; i < 8; i++)
#pragma unroll
                for (int j = 0; j < 8; j++)
                    acc[i][j] += a[i] * b[j];
        }
    }

#pragma unroll
    for (int i = 0; i < 8; i++) {
        int row = m0 + ((i < 4) ? (ty * 4 + i) : (64 + ty * 4 + (i - 4)));
        float* cp = C + (size_t)row * N + n0;
        float4 lo = make_float4(acc[i][0], acc[i][1], acc[i][2], acc[i][3]);
        float4 hi = make_float4(acc[i][4], acc[i][5], acc[i][6], acc[i][7]);
        *(float4*)(cp + tx * 4)      = lo;
        *(float4*)(cp + 64 + tx * 4) = hi;
    }
}

// =====================================================================
// RoPE (interleaved pairs). X: [M_, heads*128]. lh = log2(heads).
// =====================================================================
__global__ void rope_kernel(float* __restrict__ X,
                            const float* __restrict__ cs,
                            const float* __restrict__ sn,
                            int lh, int total)
{
    int idx = blockIdx.x * blockDim.x + threadIdx.x;
    if (idx >= total) return;
    int d2   = idx & 63;
    int rest = idx >> 6;            // row*heads + h
    int row  = rest >> lh;
    int s    = row & (S_ - 1);
    float c  = cs[s * 64 + d2];
    float sv = sn[s * 64 + d2];
    float2* p = ((float2*)X) + idx;
    float2 v = *p;
    *p = make_float2(v.x * c - v.y * sv, v.x * sv + v.y * c);
}

// =====================================================================
// Flash attention, fp32, causal, GQA (4 q-heads per kv-head).
// Block: 256 threads, tile BM=64 q rows x BN=64 kv cols, HD=128.
// Per thread: 4 S-rows (ty*4+i) x 4 S-cols (tx+16j); O: 4 rows x 8 cols.
// =====================================================================
__global__ void __launch_bounds__(256) attn_kernel(const float* __restrict__ Q,
                                                   const float* __restrict__ K,
                                                   const float* __restrict__ V,
                                                   float* __restrict__ O)
{
    extern __shared__ float sm[];
    float* Qs = sm;                    // [64][132]
    float* Ks = Qs + 64 * 132;         // [64][132]
    float* Vs = Ks + 64 * 132;         // [64][132]
    float* Ps = Vs + 64 * 132;         // [64][65]

    const int tid = threadIdx.x;
    const int tx = tid & 15;
    const int ty = tid >> 4;
    const int qt = blockIdx.x;
    const int h  = blockIdx.y;
    const int b  = blockIdx.z;
    const int hk = h >> 2;
    const int q0 = qt * 64;

    const float* qbase = Q + (size_t)(b * S_ + q0) * D_ + h * HD_;
    const float* kbase = K + (size_t)(b * S_) * KVD_ + hk * HD_;
    const float* vbase = V + (size_t)(b * S_) * KVD_ + hk * HD_;

    const float scale = 0.08838834764831845f;  // 1/sqrt(128)

    // load Q tile (scaled)
#pragma unroll
    for (int i = 0; i < 8; i++) {
        int idx = tid + i * 256;
        int r = idx >> 5, k4 = (idx & 31) << 2;
        float4 v = *(const float4*)(qbase + (size_t)r * D_ + k4);
        v.x *= scale; v.y *= scale; v.z *= scale; v.w *= scale;
        *(float4*)&Qs[r * 132 + k4] = v;
    }

    float m_i[4], l_i[4], o_acc[4][8];
#pragma unroll
    for (int i = 0; i < 4; i++) {
        m_i[i] = -1e30f; l_i[i] = 0.0f;
#pragma unroll
        for (int j = 0; j < 8; j++) o_acc[i][j] = 0.0f;
    }

    for (int t = 0; t <= qt; t++) {
        const int kv0 = t * 64;
        __syncthreads();   // protect Ks/Vs/Ps from previous iteration readers
#pragma unroll
        for (int i = 0; i < 8; i++) {
            int idx = tid + i * 256;
            int r = idx >> 5, k4 = (idx & 31) << 2;
            *(float4*)&Ks[r * 132 + k4] =
                *(const float4*)(kbase + (size_t)(kv0 + r) * KVD_ + k4);
            *(float4*)&Vs[r * 132 + k4] =
                *(const float4*)(vbase + (size_t)(kv0 + r) * KVD_ + k4);
        }
        __syncthreads();

        // S = Q * K^T (scaled already)
        float s_acc[4][4];
#pragma unroll
        for (int i = 0; i < 4; i++)
#pragma unroll
            for (int j = 0; j < 4; j++) s_acc[i][j] = 0.0f;

#pragma unroll 4
        for (int k = 0; k < HD_; k += 4) {
            float4 aq[4], bk[4];
#pragma unroll
            for (int i = 0; i < 4; i++)
                aq[i] = *(const float4*)&Qs[(ty * 4 + i) * 132 + k];
#pragma unroll
            for (int j = 0; j < 4; j++)
                bk[j] = *(const float4*)&Ks[(tx + 16 * j) * 132 + k];
#pragma unroll
            for (int i = 0; i < 4; i++)
#pragma unroll
                for (int j = 0; j < 4; j++)
                    s_acc[i][j] += aq[i].x * bk[j].x + aq[i].y * bk[j].y +
                                   aq[i].z * bk[j].z + aq[i].w * bk[j].w;
        }

        const bool diag = (t == qt);
#pragma unroll
        for (int i = 0; i < 4; i++) {
            int qrow = q0 + ty * 4 + i;
            float rmax = -1e30f;
#pragma unroll
            for (int j = 0; j < 4; j++) {
                int kcol = kv0 + tx + 16 * j;
                if (diag && kcol > qrow) s_acc[i][j] = -1e30f;
                rmax = fmaxf(rmax, s_acc[i][j]);
            }
            rmax = fmaxf(rmax, __shfl_xor_sync(0xffffffffu, rmax, 1));
            rmax = fmaxf(rmax, __shfl_xor_sync(0xffffffffu, rmax, 2));
            rmax = fmaxf(rmax, __shfl_xor_sync(0xffffffffu, rmax, 4));
            rmax = fmaxf(rmax, __shfl_xor_sync(0xffffffffu, rmax, 8));

            float mnew  = fmaxf(m_i[i], rmax);
            float alpha = __expf(m_i[i] - mnew);
            m_i[i] = mnew;

            float p[4];
            float rsum = 0.0f;
#pragma unroll
            for (int j = 0; j < 4; j++) {
                p[j] = __expf(s_acc[i][j] - mnew);
                rsum += p[j];
            }
            rsum += __shfl_xor_sync(0xffffffffu, rsum, 1);
            rsum += __shfl_xor_sync(0xffffffffu, rsum, 2);
            rsum += __shfl_xor_sync(0xffffffffu, rsum, 4);
            rsum += __shfl_xor_sync(0xffffffffu, rsum, 8);

            l_i[i] = l_i[i] * alpha + rsum;
#pragma unroll
            for (int jj = 0; jj < 8; jj++) o_acc[i][jj] *= alpha;
#pragma unroll
            for (int j = 0; j < 4; j++)
                Ps[(ty * 4 + i) * 65 + tx + 16 * j] = p[j];
        }
        __syncthreads();

        // O += P * V
#pragma unroll 4
        for (int c = 0; c < 64; c++) {
            float4 vlo = *(const float4*)&Vs[c * 132 + tx * 4];
            float4 vhi = *(const float4*)&Vs[c * 132 + 64 + tx * 4];
#pragma unroll
            for (int i = 0; i < 4; i++) {
                float pp = Ps[(ty * 4 + i) * 65 + c];
                o_acc[i][0] += pp * vlo.x; o_acc[i][1] += pp * vlo.y;
                o_acc[i][2] += pp * vlo.z; o_acc[i][3] += pp * vlo.w;
                o_acc[i][4] += pp * vhi.x; o_acc[i][5] += pp * vhi.y;
                o_acc[i][6] += pp * vhi.z; o_acc[i][7] += pp * vhi.w;
            }
        }
    }

    // normalize + store
#pragma unroll
    for (int i = 0; i < 4; i++) {
        float inv_l = 1.0f / l_i[i];
        int row = b * S_ + q0 + ty * 4 + i;
        float* op = O + (size_t)row * D_ + h * HD_;
        float4 lo = make_float4(o_acc[i][0] * inv_l, o_acc[i][1] * inv_l,
                                o_acc[i][2] * inv_l, o_acc[i][3] * inv_l);
        float4 hi = make_float4(o_acc[i][4] * inv_l, o_acc[i][5] * inv_l,
                                o_acc[i][6] * inv_l, o_acc[i][7] * inv_l);
        *(float4*)(op + tx * 4)      = lo;
        *(float4*)(op + 64 + tx * 4) = hi;
    }
}

// =====================================================================
// launch
// =====================================================================
extern "C" void kernel_launch(void* const* d_in, const int* in_sizes, int n_in,
                              void* d_out, int out_size)
{
    const float* x  = (const float*)d_in[0];
    const float* fc = (const float*)d_in[1];
    const float* fs = (const float*)d_in[2];
    const float* wq = (const float*)d_in[3];
    const float* wk = (const float*)d_in[4];
    const float* wv = (const float*)d_in[5];
    const float* wo = (const float*)d_in[6];
    float* out = (float*)d_out;

    float *q, *k, *v, *attn;
    cudaGetSymbolAddress((void**)&q,    g_q);
    cudaGetSymbolAddress((void**)&k,    g_k);
    cudaGetSymbolAddress((void**)&v,    g_v);
    cudaGetSymbolAddress((void**)&attn, g_attn);

    // QKV projections
    sgemm_nt<<<dim3(32, 32), 256>>>(x, wq, q, M_, D_,   D_);
    sgemm_nt<<<dim3(8,  32), 256>>>(x, wk, k, M_, KVD_, D_);
    sgemm_nt<<<dim3(8,  32), 256>>>(x, wv, v, M_, KVD_, D_);

    // RoPE
    {
        int tq = M_ * H_ * 64;
        rope_kernel<<<(tq + 255) / 256, 256>>>(q, fc, fs, 5, tq);
        int tk = M_ * HK_ * 64;
        rope_kernel<<<(tk + 255) / 256, 256>>>(k, fc, fs, 3, tk);
    }

    // attention
    {
        const int SMEM = (3 * 64 * 132 + 64 * 65) * 4;  // 118016 bytes
        cudaFuncSetAttribute(attn_kernel,
                             cudaFuncAttributeMaxDynamicSharedMemorySize, SMEM);
        attn_kernel<<<dim3(S_ / 64, H_, B_), 256, SMEM>>>(q, k, v, attn);
    }

    // output projection
    sgemm_nt<<<dim3(32, 32), 256>>>(attn, wo, out, M_, D_, D_);
}

// round 2
// speedup vs baseline: 1.7788x; 1.7788x over previous
#include <cuda_runtime.h>
#include <math.h>

#define B_   2
#define S_   2048
#define D_   4096
#define H_   32
#define HK_  8
#define HD_  128
#define M_   (B_ * S_)          // 4096 total tokens
#define KVD_ (HK_ * HD_)        // 1024

// ---------------- scratch (device globals; no allocation allowed) ----------------
__device__ float g_q[(size_t)M_ * D_];        // 4096 x 4096  (67 MB)
__device__ float g_k[(size_t)M_ * KVD_];      // 4096 x 1024
__device__ float g_v[(size_t)M_ * KVD_];      // 4096 x 1024
__device__ float g_attn[(size_t)M_ * D_];     // 4096 x 4096

// =====================================================================
// TF32 tensor-core GEMM: C[M,N] = A[M,K] * B[N,K]^T   (row-major)
// Block tile 128x128, BK=16, 256 threads = 8 warps (2x4 warp grid),
// each warp: 64x32 = 4x4 tiles of m16n8k8 mma.
// =====================================================================
__device__ __forceinline__ unsigned f2tf32(float x) {
    unsigned y;
    asm("cvt.rna.tf32.f32 %0, %1;" : "=r"(y) : "f"(x));
    return y;
}

__device__ __forceinline__ void mma_tf32(float& c0, float& c1, float& c2, float& c3,
                                         unsigned a0, unsigned a1, unsigned a2, unsigned a3,
                                         unsigned b0, unsigned b1) {
    asm volatile(
        "mma.sync.aligned.m16n8k8.row.col.f32.tf32.tf32.f32 "
        "{%0,%1,%2,%3}, {%4,%5,%6,%7}, {%8,%9}, {%0,%1,%2,%3};\n"
        : "+f"(c0), "+f"(c1), "+f"(c2), "+f"(c3)
        : "r"(a0), "r"(a1), "r"(a2), "r"(a3), "r"(b0), "r"(b1));
}

#define LDA 20   // smem row stride (floats): conflict-free fragment loads

__global__ void __launch_bounds__(256) gemm_tf32(const float* __restrict__ A,
                                                 const float* __restrict__ Bm,
                                                 float* __restrict__ C,
                                                 int M, int N, int K)
{
    __shared__ unsigned As[128 * LDA];
    __shared__ unsigned Bs[128 * LDA];

    const int tid  = threadIdx.x;
    const int lane = tid & 31;
    const int warp = tid >> 5;
    const int m0 = blockIdx.y << 7;
    const int n0 = blockIdx.x << 7;

    const int wm = (warp >> 2) * 64;   // warp row offset within tile
    const int wn = (warp & 3) * 32;    // warp col offset within tile
    const int grp = lane >> 2;         // 0..7
    const int qid = lane & 3;          // 0..3

    // global load mapping: each thread loads 8 floats of A and 8 of B per BK
    const int lr = tid >> 1;           // 0..127 row within tile
    const int lc = (tid & 1) * 8;      // 0 or 8
    const float* ap = A  + (size_t)(m0 + lr) * K + lc;
    const float* bp = Bm + (size_t)(n0 + lr) * K + lc;

    float acc[4][4][4];                // [mi][nj][c0..c3]
#pragma unroll
    for (int i = 0; i < 4; i++)
#pragma unroll
        for (int j = 0; j < 4; j++)
#pragma unroll
            for (int c = 0; c < 4; c++) acc[i][j][c] = 0.0f;

    const unsigned* a_base = As + (wm + grp) * LDA + qid;
    const unsigned* b_base = Bs + (wn + grp) * LDA + qid;

    for (int kb = 0; kb < K; kb += 16) {
        float4 av0 = *(const float4*)(ap + kb);
        float4 av1 = *(const float4*)(ap + kb + 4);
        float4 bv0 = *(const float4*)(bp + kb);
        float4 bv1 = *(const float4*)(bp + kb + 4);

        __syncthreads();
        unsigned* as = As + lr * LDA + lc;
        as[0] = f2tf32(av0.x); as[1] = f2tf32(av0.y);
        as[2] = f2tf32(av0.z); as[3] = f2tf32(av0.w);
        as[4] = f2tf32(av1.x); as[5] = f2tf32(av1.y);
        as[6] = f2tf32(av1.z); as[7] = f2tf32(av1.w);
        unsigned* bs = Bs + lr * LDA + lc;
        bs[0] = f2tf32(bv0.x); bs[1] = f2tf32(bv0.y);
        bs[2] = f2tf32(bv0.z); bs[3] = f2tf32(bv0.w);
        bs[4] = f2tf32(bv1.x); bs[5] = f2tf32(bv1.y);
        bs[6] = f2tf32(bv1.z); bs[7] = f2tf32(bv1.w);
        __syncthreads();

#pragma unroll
        for (int kk = 0; kk < 16; kk += 8) {
            unsigned af[4][4], bf[4][2];
#pragma unroll
            for (int i = 0; i < 4; i++) {
                const unsigned* p = a_base + i * 16 * LDA + kk;
                af[i][0] = p[0];
                af[i][1] = p[8 * LDA];
                af[i][2] = p[4];
                af[i][3] = p[8 * LDA + 4];
            }
#pragma unroll
            for (int j = 0; j < 4; j++) {
                const unsigned* p = b_base + j * 8 * LDA + kk;
                bf[j][0] = p[0];
                bf[j][1] = p[4];
            }
#pragma unroll
            for (int i = 0; i < 4; i++)
#pragma unroll
                for (int j = 0; j < 4; j++)
                    mma_tf32(acc[i][j][0], acc[i][j][1], acc[i][j][2], acc[i][j][3],
                             af[i][0], af[i][1], af[i][2], af[i][3],
                             bf[j][0], bf[j][1]);
        }
    }

    // epilogue: c0,c1 -> (row, col), (row, col+1); c2,c3 -> row+8
#pragma unroll
    for (int i = 0; i < 4; i++) {
        int row = m0 + wm + i * 16 + grp;
#pragma unroll
        for (int j = 0; j < 4; j++) {
            int col = n0 + wn + j * 8 + qid * 2;
            float* cp0 = C + (size_t)row * N + col;
            float* cp1 = C + (size_t)(row + 8) * N + col;
            *(float2*)cp0 = make_float2(acc[i][j][0], acc[i][j][1]);
            *(float2*)cp1 = make_float2(acc[i][j][2], acc[i][j][3]);
        }
    }
}

// =====================================================================
// RoPE (interleaved pairs). X: [M_, heads*128]. lh = log2(heads).
// =====================================================================
__global__ void rope_kernel(float* __restrict__ X,
                            const float* __restrict__ cs,
                            const float* __restrict__ sn,
                            int lh, int total)
{
    int idx = blockIdx.x * blockDim.x + threadIdx.x;
    if (idx >= total) return;
    int d2   = idx & 63;
    int rest = idx >> 6;            // row*heads + h
    int row  = rest >> lh;
    int s    = row & (S_ - 1);
    float c  = cs[s * 64 + d2];
    float sv = sn[s * 64 + d2];
    float2* p = ((float2*)X) + idx;
    float2 v = *p;
    *p = make_float2(v.x * c - v.y * sv, v.x * sv + v.y * c);
}

// =====================================================================
// Flash attention, fp32, causal, GQA (4 q-heads per kv-head).
// Block: 256 threads, tile BM=64 q rows x BN=64 kv cols, HD=128.
// =====================================================================
__global__ void __launch_bounds__(256) attn_kernel(const float* __restrict__ Q,
                                                   const float* __restrict__ K,
                                                   const float* __restrict__ V,
                                                   float* __restrict__ O)
{
    extern __shared__ float sm[];
    float* Qs = sm;                    // [64][132]
    float* Ks = Qs + 64 * 132;         // [64][132]
    float* Vs = Ks + 64 * 132;         // [64][132]
    float* Ps = Vs + 64 * 132;         // [64][65]

    const int tid = threadIdx.x;
    const int tx = tid & 15;
    const int ty = tid >> 4;
    const int qt = blockIdx.x;
    const int h  = blockIdx.y;
    const int b  = blockIdx.z;
    const int hk = h >> 2;
    const int q0 = qt * 64;

    const float* qbase = Q + (size_t)(b * S_ + q0) * D_ + h * HD_;
    const float* kbase = K + (size_t)(b * S_) * KVD_ + hk * HD_;
    const float* vbase = V + (size_t)(b * S_) * KVD_ + hk * HD_;

    const float scale = 0.08838834764831845f;  // 1/sqrt(128)

#pragma unroll
    for (int i = 0; i < 8; i++) {
        int idx = tid + i * 256;
        int r = idx >> 5, k4 = (idx & 31) << 2;
        float4 v = *(const float4*)(qbase + (size_t)r * D_ + k4);
        v.x *= scale; v.y *= scale; v.z *= scale; v.w *= scale;
        *(float4*)&Qs[r * 132 + k4] = v;
    }

    float m_i[4], l_i[4], o_acc[4][8];
#pragma unroll
    for (int i = 0; i < 4; i++) {
        m_i[i] = -1e30f; l_i[i] = 0.0f;
#pragma unroll
        for (int j = 0; j < 8; j++) o_acc[i][j] = 0.0f;
    }

    for (int t = 0; t <= qt; t++) {
        const int kv0 = t * 64;
        __syncthreads();
#pragma unroll
        for (int i = 0; i < 8; i++) {
            int idx = tid + i * 256;
            int r = idx >> 5, k4 = (idx & 31) << 2;
            *(float4*)&Ks[r * 132 + k4] =
                *(const float4*)(kbase + (size_t)(kv0 + r) * KVD_ + k4);
            *(float4*)&Vs[r * 132 + k4] =
                *(const float4*)(vbase + (size_t)(kv0 + r) * KVD_ + k4);
        }
        __syncthreads();

        float s_acc[4][4];
#pragma unroll
        for (int i = 0; i < 4; i++)
#pragma unroll
            for (int j = 0; j < 4; j++) s_acc[i][j] = 0.0f;

#pragma unroll 4
        for (int k = 0; k < HD_; k += 4) {
            float4 aq[4], bk[4];
#pragma unroll
            for (int i = 0; i < 4; i++)
                aq[i] = *(const float4*)&Qs[(ty * 4 + i) * 132 + k];
#pragma unroll
            for (int j = 0; j < 4; j++)
                bk[j] = *(const float4*)&Ks[(tx + 16 * j) * 132 + k];
#pragma unroll
            for (int i = 0; i < 4; i++)
#pragma unroll
                for (int j = 0; j < 4; j++)
                    s_acc[i][j] += aq[i].x * bk[j].x + aq[i].y * bk[j].y +
                                   aq[i].z * bk[j].z + aq[i].w * bk[j].w;
        }

        const bool diag = (t == qt);
#pragma unroll
        for (int i = 0; i < 4; i++) {
            int qrow = q0 + ty * 4 + i;
            float rmax = -1e30f;
#pragma unroll
            for (int j = 0; j < 4; j++) {
                int kcol = kv0 + tx + 16 * j;
                if (diag && kcol > qrow) s_acc[i][j] = -1e30f;
                rmax = fmaxf(rmax, s_acc[i][j]);
            }
            rmax = fmaxf(rmax, __shfl_xor_sync(0xffffffffu, rmax, 1));
            rmax = fmaxf(rmax, __shfl_xor_sync(0xffffffffu, rmax, 2));
            rmax = fmaxf(rmax, __shfl_xor_sync(0xffffffffu, rmax, 4));
            rmax = fmaxf(rmax, __shfl_xor_sync(0xffffffffu, rmax, 8));

            float mnew  = fmaxf(m_i[i], rmax);
            float alpha = __expf(m_i[i] - mnew);
            m_i[i] = mnew;

            float p[4];
            float rsum = 0.0f;
#pragma unroll
            for (int j = 0; j < 4; j++) {
                p[j] = __expf(s_acc[i][j] - mnew);
                rsum += p[j];
            }
            rsum += __shfl_xor_sync(0xffffffffu, rsum, 1);
            rsum += __shfl_xor_sync(0xffffffffu, rsum, 2);
            rsum += __shfl_xor_sync(0xffffffffu, rsum, 4);
            rsum += __shfl_xor_sync(0xffffffffu, rsum, 8);

            l_i[i] = l_i[i] * alpha + rsum;
#pragma unroll
            for (int jj = 0; jj < 8; jj++) o_acc[i][jj] *= alpha;
#pragma unroll
            for (int j = 0; j < 4; j++)
                Ps[(ty * 4 + i) * 65 + tx + 16 * j] = p[j];
        }
        __syncthreads();

#pragma unroll 4
        for (int c = 0; c < 64; c++) {
            float4 vlo = *(const float4*)&Vs[c * 132 + tx * 4];
            float4 vhi = *(const float4*)&Vs[c * 132 + 64 + tx * 4];
#pragma unroll
            for (int i = 0; i < 4; i++) {
                float pp = Ps[(ty * 4 + i) * 65 + c];
                o_acc[i][0] += pp * vlo.x; o_acc[i][1] += pp * vlo.y;
                o_acc[i][2] += pp * vlo.z; o_acc[i][3] += pp * vlo.w;
                o_acc[i][4] += pp * vhi.x; o_acc[i][5] += pp * vhi.y;
                o_acc[i][6] += pp * vhi.z; o_acc[i][7] += pp * vhi.w;
            }
        }
    }

#pragma unroll
    for (int i = 0; i < 4; i++) {
        float inv_l = 1.0f / l_i[i];
        int row = b * S_ + q0 + ty * 4 + i;
        float* op = O + (size_t)row * D_ + h * HD_;
        float4 lo = make_float4(o_acc[i][0] * inv_l, o_acc[i][1] * inv_l,
                                o_acc[i][2] * inv_l, o_acc[i][3] * inv_l);
        float4 hi = make_float4(o_acc[i][4] * inv_l, o_acc[i][5] * inv_l,
                                o_acc[i][6] * inv_l, o_acc[i][7] * inv_l);
        *(float4*)(op + tx * 4)      = lo;
        *(float4*)(op + 64 + tx * 4) = hi;
    }
}

// =====================================================================
// launch
// =====================================================================
extern "C" void kernel_launch(void* const* d_in, const int* in_sizes, int n_in,
                              void* d_out, int out_size)
{
    const float* x  = (const float*)d_in[0];
    const float* fc = (const float*)d_in[1];
    const float* fs = (const float*)d_in[2];
    const float* wq = (const float*)d_in[3];
    const float* wk = (const float*)d_in[4];
    const float* wv = (const float*)d_in[5];
    const float* wo = (const float*)d_in[6];
    float* out = (float*)d_out;

    float *q, *k, *v, *attn;
    cudaGetSymbolAddress((void**)&q,    g_q);
    cudaGetSymbolAddress((void**)&k,    g_k);
    cudaGetSymbolAddress((void**)&v,    g_v);
    cudaGetSymbolAddress((void**)&attn, g_attn);

    // QKV projections (tf32 tensor cores)
    gemm_tf32<<<dim3(32, 32), 256>>>(x, wq, q, M_, D_,   D_);
    gemm_tf32<<<dim3(8,  32), 256>>>(x, wk, k, M_, KVD_, D_);
    gemm_tf32<<<dim3(8,  32), 256>>>(x, wv, v, M_, KVD_, D_);

    // RoPE
    {
        int tq = M_ * H_ * 64;
        rope_kernel<<<(tq + 255) / 256, 256>>>(q, fc, fs, 5, tq);
        int tk = M_ * HK_ * 64;
        rope_kernel<<<(tk + 255) / 256, 256>>>(k, fc, fs, 3, tk);
    }

    // attention (fp32 SIMT flash)
    {
        const int SMEM = (3 * 64 * 132 + 64 * 65) * 4;  // 118016 bytes
        cudaFuncSetAttribute(attn_kernel,
                             cudaFuncAttributeMaxDynamicSharedMemorySize, SMEM);
        attn_kernel<<<dim3(S_ / 64, H_, B_), 256, SMEM>>>(q, k, v, attn);
    }

    // output projection (tf32 tensor cores)
    gemm_tf32<<<dim3(32, 32), 256>>>(attn, wo, out, M_, D_, D_);
}

// round 3
// speedup vs baseline: 2.0302x; 1.1414x over previous
#include <cuda_runtime.h>
#include <cuda_bf16.h>
#include <math.h>

#define B_   2
#define S_   2048
#define D_   4096
#define H_   32
#define HK_  8
#define HD_  128
#define M_   (B_ * S_)          // 4096 total tokens
#define KVD_ (HK_ * HD_)        // 1024
#define DP_  (D_ / 2)           // 2048 pairs per row (K=4096)

// ---------------- scratch (device globals; no allocation allowed) ----------------
__device__ float    g_q[(size_t)M_ * D_];
__device__ float    g_k[(size_t)M_ * KVD_];
__device__ float    g_v[(size_t)M_ * KVD_];
// split planes (bf16 pairs packed in u32): [rows][K/2]
__device__ unsigned g_xh[(size_t)M_ * DP_],   g_xl[(size_t)M_ * DP_];
__device__ unsigned g_wqh[(size_t)D_ * DP_],  g_wql[(size_t)D_ * DP_];
__device__ unsigned g_wkh[(size_t)KVD_ * DP_],g_wkl[(size_t)KVD_ * DP_];
__device__ unsigned g_wvh[(size_t)KVD_ * DP_],g_wvl[(size_t)KVD_ * DP_];
__device__ unsigned g_woh[(size_t)D_ * DP_],  g_wol[(size_t)D_ * DP_];
__device__ unsigned g_ah[(size_t)M_ * DP_],   g_al[(size_t)M_ * DP_];  // attention out

// ---------------- helpers ----------------
__device__ __forceinline__ void split2(float x, float y, unsigned& hi, unsigned& lo) {
    __nv_bfloat16 xh = __float2bfloat16_rn(x);
    __nv_bfloat16 yh = __float2bfloat16_rn(y);
    __nv_bfloat16 xl = __float2bfloat16_rn(x - __bfloat162float(xh));
    __nv_bfloat16 yl = __float2bfloat16_rn(y - __bfloat162float(yh));
    hi = (unsigned)__bfloat16_as_ushort(xh) | ((unsigned)__bfloat16_as_ushort(yh) << 16);
    lo = (unsigned)__bfloat16_as_ushort(xl) | ((unsigned)__bfloat16_as_ushort(yl) << 16);
}

__device__ __forceinline__ void mma_bf16(float* c, const unsigned* a, unsigned b0, unsigned b1) {
    asm volatile(
        "mma.sync.aligned.m16n8k16.row.col.f32.bf16.bf16.f32 "
        "{%0,%1,%2,%3}, {%4,%5,%6,%7}, {%8,%9}, {%0,%1,%2,%3};\n"
        : "+f"(c[0]), "+f"(c[1]), "+f"(c[2]), "+f"(c[3])
        : "r"(a[0]), "r"(a[1]), "r"(a[2]), "r"(a[3]), "r"(b0), "r"(b1));
}

__device__ __forceinline__ void mma3(float* c, const unsigned* ah, const unsigned* al,
                                     unsigned b0h, unsigned b1h, unsigned b0l, unsigned b1l) {
    mma_bf16(c, ah, b0h, b1h);
    mma_bf16(c, ah, b0l, b1l);
    mma_bf16(c, al, b0h, b1h);
}

__device__ __forceinline__ void cpa16(unsigned saddr, const void* g) {
    asm volatile("cp.async.cg.shared.global [%0], [%1], 16;" :: "r"(saddr), "l"(g));
}

// ---------------- split pass: fp32 -> bf16 hi/lo planes ----------------
__global__ void split_kernel(const float* __restrict__ X,
                             unsigned* __restrict__ Hh, unsigned* __restrict__ Ll,
                             int npairs)
{
    int i = blockIdx.x * blockDim.x + threadIdx.x;
    if (i >= npairs) return;
    float2 v = ((const float2*)X)[i];
    split2(v.x, v.y, Hh[i], Ll[i]);
}

// =====================================================================
// bf16x3 GEMM: C[M,N] = A[M,K] * B[N,K]^T, A/B given as hi/lo pair planes.
// 128x128 block tile, BK=32 (16 pairs), 256 threads, cp.async 2-stage.
// Warp: 64x32 (4x4 of m16n8k16).
// =====================================================================
#define GSTR 20                  // smem row stride in u32 (16 pairs + pad), == 4 mod 32
#define GPL  (128 * GSTR)        // plane size (u32)

__global__ void __launch_bounds__(256) gemm3(const unsigned* __restrict__ Ah,
                                             const unsigned* __restrict__ Al,
                                             const unsigned* __restrict__ Bh,
                                             const unsigned* __restrict__ Bl,
                                             float* __restrict__ C,
                                             int M, int N, int K)
{
    extern __shared__ unsigned gs[];      // 2 stages x 4 planes x GPL

    const int tid  = threadIdx.x;
    const int lane = tid & 31;
    const int warp = tid >> 5;
    const int m0 = blockIdx.y << 7;
    const int n0 = blockIdx.x << 7;
    const int wm = (warp >> 2) * 64;
    const int wn = (warp & 3) * 32;
    const int grp = lane >> 2;
    const int qid = lane & 3;
    const int KP = K >> 1;

    const int lr = tid >> 1;
    const int lc = (tid & 1) * 8;
    const unsigned* agh = Ah + (size_t)(m0 + lr) * KP + lc;
    const unsigned* agl = Al + (size_t)(m0 + lr) * KP + lc;
    const unsigned* bgh = Bh + (size_t)(n0 + lr) * KP + lc;
    const unsigned* bgl = Bl + (size_t)(n0 + lr) * KP + lc;

    unsigned sbase = (unsigned)__cvta_generic_to_shared(gs);
    const unsigned srow = (lr * GSTR + lc) * 4;   // byte offset within plane

    float acc[4][4][4];
#pragma unroll
    for (int i = 0; i < 4; i++)
#pragma unroll
        for (int j = 0; j < 4; j++)
#pragma unroll
            for (int c = 0; c < 4; c++) acc[i][j][c] = 0.0f;

    const int nchunks = K / 32;

    auto issue = [&](int s, int chunk) {
        unsigned st = sbase + (unsigned)(s * 4 * GPL * 4) + srow;
        const int go = chunk * 16;
        cpa16(st,                 agh + go);     cpa16(st + 16,                 agh + go + 4);
        cpa16(st + GPL * 4,       agl + go);     cpa16(st + GPL * 4 + 16,       agl + go + 4);
        cpa16(st + 2 * GPL * 4,   bgh + go);     cpa16(st + 2 * GPL * 4 + 16,   bgh + go + 4);
        cpa16(st + 3 * GPL * 4,   bgl + go);     cpa16(st + 3 * GPL * 4 + 16,   bgl + go + 4);
    };

    issue(0, 0);
    asm volatile("cp.async.commit_group;");

    for (int c = 0; c < nchunks; c++) {
        if (c + 1 < nchunks) issue((c + 1) & 1, c + 1);
        asm volatile("cp.async.commit_group;");
        asm volatile("cp.async.wait_group %0;" :: "n"(1));
        __syncthreads();

        const unsigned* Ash = gs + (c & 1) * 4 * GPL;
        const unsigned* Asl = Ash + GPL;
        const unsigned* Bsh = Ash + 2 * GPL;
        const unsigned* Bsl = Ash + 3 * GPL;

#pragma unroll
        for (int kk = 0; kk < 2; kk++) {
            unsigned ah[4][4], al[4][4], bh[4][2], bl[4][2];
#pragma unroll
            for (int mi = 0; mi < 4; mi++) {
                const unsigned* p = Ash + (wm + mi * 16 + grp) * GSTR + kk * 8 + qid;
                ah[mi][0] = p[0]; ah[mi][1] = p[8 * GSTR];
                ah[mi][2] = p[4]; ah[mi][3] = p[8 * GSTR + 4];
                const unsigned* q = Asl + (wm + mi * 16 + grp) * GSTR + kk * 8 + qid;
                al[mi][0] = q[0]; al[mi][1] = q[8 * GSTR];
                al[mi][2] = q[4]; al[mi][3] = q[8 * GSTR + 4];
            }
#pragma unroll
            for (int nj = 0; nj < 4; nj++) {
                const unsigned* p = Bsh + (wn + nj * 8 + grp) * GSTR + kk * 8 + qid;
                bh[nj][0] = p[0]; bh[nj][1] = p[4];
                const unsigned* q = Bsl + (wn + nj * 8 + grp) * GSTR + kk * 8 + qid;
                bl[nj][0] = q[0]; bl[nj][1] = q[4];
            }
#pragma unroll
            for (int mi = 0; mi < 4; mi++)
#pragma unroll
                for (int nj = 0; nj < 4; nj++)
                    mma3(acc[mi][nj], ah[mi], al[mi],
                         bh[nj][0], bh[nj][1], bl[nj][0], bl[nj][1]);
        }
        __syncthreads();
    }

#pragma unroll
    for (int mi = 0; mi < 4; mi++) {
        int row0 = m0 + wm + mi * 16 + grp;
#pragma unroll
        for (int nj = 0; nj < 4; nj++) {
            int col = n0 + wn + nj * 8 + qid * 2;
            *(float2*)(C + (size_t)row0 * N + col)       = make_float2(acc[mi][nj][0], acc[mi][nj][1]);
            *(float2*)(C + (size_t)(row0 + 8) * N + col) = make_float2(acc[mi][nj][2], acc[mi][nj][3]);
        }
    }
}

// =====================================================================
// RoPE (interleaved pairs). X: [M_, heads*128]. lh = log2(heads).
// =====================================================================
__global__ void rope_kernel(float* __restrict__ X,
                            const float* __restrict__ cs,
                            const float* __restrict__ sn,
                            int lh, int total)
{
    int idx = blockIdx.x * blockDim.x + threadIdx.x;
    if (idx >= total) return;
    int d2   = idx & 63;
    int rest = idx >> 6;
    int row  = rest >> lh;
    int s    = row & (S_ - 1);
    float c  = cs[s * 64 + d2];
    float sv = sn[s * 64 + d2];
    float2* p = ((float2*)X) + idx;
    float2 v = *p;
    *p = make_float2(v.x * c - v.y * sv, v.x * sv + v.y * c);
}

// =====================================================================
// Flash attention, bf16x3 tensor cores, causal, GQA.
// BM=128 q rows per CTA, BN=64 kv per tile, HD=128. 256 threads = 8 warps,
// each warp owns 16 q rows x full kv width. Outputs split planes.
// =====================================================================
#define KSTR 68    // K smem stride (64 pairs + 4)
#define VSTR 36    // Vt/P smem stride (32 pairs + 4)

__global__ void __launch_bounds__(256) attn_mma(const float* __restrict__ Q,
                                                const float* __restrict__ K,
                                                const float* __restrict__ V,
                                                unsigned* __restrict__ Oh,
                                                unsigned* __restrict__ Ol)
{
    extern __shared__ unsigned smu[];
    unsigned* Kh  = smu;                    // [64][KSTR]
    unsigned* Kl  = Kh  + 64 * KSTR;
    unsigned* Vth = Kl  + 64 * KSTR;        // [128][VSTR]  (d-major, kv pairs)
    unsigned* Vtl = Vth + 128 * VSTR;
    unsigned* Ph  = Vtl + 128 * VSTR;       // [128][VSTR]
    unsigned* Pl  = Ph  + 128 * VSTR;

    const int tid  = threadIdx.x;
    const int lane = tid & 31;
    const int warp = tid >> 5;
    const int grp  = lane >> 2;
    const int qid  = lane & 3;
    const int qt = blockIdx.x;
    const int h  = blockIdx.y;
    const int b  = blockIdx.z;
    const int hk = h >> 2;
    const int q0  = qt * 128;
    const int wq0 = warp * 16;

    // ---- Q fragments in registers (scaled + split) ----
    unsigned qh[8][4], ql[8][4];
    {
        const float scale = 0.08838834764831845f;
        const float* qb = Q + (size_t)(b * S_ + q0 + wq0) * D_ + h * HD_;
#pragma unroll
        for (int kk = 0; kk < 8; kk++) {
            float2 v;
            v = *(const float2*)(qb + (size_t)grp * D_ + kk * 16 + 2 * qid);
            split2(v.x * scale, v.y * scale, qh[kk][0], ql[kk][0]);
            v = *(const float2*)(qb + (size_t)(grp + 8) * D_ + kk * 16 + 2 * qid);
            split2(v.x * scale, v.y * scale, qh[kk][1], ql[kk][1]);
            v = *(const float2*)(qb + (size_t)grp * D_ + kk * 16 + 2 * qid + 8);
            split2(v.x * scale, v.y * scale, qh[kk][2], ql[kk][2]);
            v = *(const float2*)(qb + (size_t)(grp + 8) * D_ + kk * 16 + 2 * qid + 8);
            split2(v.x * scale, v.y * scale, qh[kk][3], ql[kk][3]);
        }
    }

    float o_acc[16][4];
#pragma unroll
    for (int i = 0; i < 16; i++)
#pragma unroll
        for (int c = 0; c < 4; c++) o_acc[i][c] = 0.0f;
    float m0r = -1e30f, m1r = -1e30f, l0r = 0.0f, l1r = 0.0f;

    const float* kbase = K + (size_t)(b * S_) * KVD_ + hk * HD_;
    const float* vbase = V + (size_t)(b * S_) * KVD_ + hk * HD_;
    const int qrow0 = q0 + wq0 + grp;     // row for c0/c1; +8 for c2/c3
    const int tmax = 2 * qt + 1;

    const int lr = tid >> 2;              // 0..63  (K/V load row)
    const int ld0 = (tid & 3) * 32;       // d base

    for (int t = 0; t <= tmax; t++) {
        const int kv0 = t * 64;
        __syncthreads();
        // ---- load + split K tile [64][128] ----
        {
            const float* kp = kbase + (size_t)(kv0 + lr) * KVD_ + ld0;
            unsigned* khr = Kh + lr * KSTR + ld0 / 2;
            unsigned* klr = Kl + lr * KSTR + ld0 / 2;
#pragma unroll
            for (int i = 0; i < 8; i++) {
                float4 v = *(const float4*)(kp + i * 4);
                split2(v.x, v.y, khr[i * 2],     klr[i * 2]);
                split2(v.z, v.w, khr[i * 2 + 1], klr[i * 2 + 1]);
            }
            // ---- load + split + transpose V tile -> Vt[d][kv pairs] ----
            const float* vp = vbase + (size_t)(kv0 + lr) * KVD_ + ld0;
            __nv_bfloat16* vh16 = (__nv_bfloat16*)Vth;
            __nv_bfloat16* vl16 = (__nv_bfloat16*)Vtl;
            const int half = lr & 1, rp = lr >> 1;
#pragma unroll
            for (int i = 0; i < 8; i++) {
                float4 v = *(const float4*)(vp + i * 4);
                float vv[4] = {v.x, v.y, v.z, v.w};
#pragma unroll
                for (int j = 0; j < 4; j++) {
                    int d = ld0 + i * 4 + j;
                    __nv_bfloat16 hb = __float2bfloat16_rn(vv[j]);
                    __nv_bfloat16 lb = __float2bfloat16_rn(vv[j] - __bfloat162float(hb));
                    vh16[(d * VSTR + rp) * 2 + half] = hb;
                    vl16[(d * VSTR + rp) * 2 + half] = lb;
                }
            }
        }
        __syncthreads();

        if (kv0 > q0 + wq0 + 15) continue;   // fully masked for this warp

        // ---- S = Q K^T ----
        float s[8][4];
#pragma unroll
        for (int nj = 0; nj < 8; nj++)
#pragma unroll
            for (int c = 0; c < 4; c++) s[nj][c] = 0.0f;

#pragma unroll
        for (int kk = 0; kk < 8; kk++) {
#pragma unroll
            for (int nj = 0; nj < 8; nj++) {
                const unsigned* ph = Kh + (nj * 8 + grp) * KSTR + kk * 8 + qid;
                const unsigned* pl = Kl + (nj * 8 + grp) * KSTR + kk * 8 + qid;
                mma3(s[nj], qh[kk], ql[kk], ph[0], ph[4], pl[0], pl[4]);
            }
        }

        // ---- causal mask (only when tile crosses this warp's diagonal) ----
        if (kv0 + 63 > q0 + wq0) {
#pragma unroll
            for (int nj = 0; nj < 8; nj++) {
                int kcol = kv0 + nj * 8 + 2 * qid;
                if (kcol     > qrow0)     s[nj][0] = -1e30f;
                if (kcol + 1 > qrow0)     s[nj][1] = -1e30f;
                if (kcol     > qrow0 + 8) s[nj][2] = -1e30f;
                if (kcol + 1 > qrow0 + 8) s[nj][3] = -1e30f;
            }
        }

        // ---- online softmax (two rows per thread) ----
        float rm0 = -1e30f, rm1 = -1e30f;
#pragma unroll
        for (int nj = 0; nj < 8; nj++) {
            rm0 = fmaxf(rm0, fmaxf(s[nj][0], s[nj][1]));
            rm1 = fmaxf(rm1, fmaxf(s[nj][2], s[nj][3]));
        }
        rm0 = fmaxf(rm0, __shfl_xor_sync(0xffffffffu, rm0, 1));
        rm0 = fmaxf(rm0, __shfl_xor_sync(0xffffffffu, rm0, 2));
        rm1 = fmaxf(rm1, __shfl_xor_sync(0xffffffffu, rm1, 1));
        rm1 = fmaxf(rm1, __shfl_xor_sync(0xffffffffu, rm1, 2));

        float mn0 = fmaxf(m0r, rm0), mn1 = fmaxf(m1r, rm1);
        float a0 = __expf(m0r - mn0), a1 = __expf(m1r - mn1);
        m0r = mn0; m1r = mn1;

        float rs0 = 0.0f, rs1 = 0.0f;
#pragma unroll
        for (int nj = 0; nj < 8; nj++) {
            s[nj][0] = __expf(s[nj][0] - mn0);
            s[nj][1] = __expf(s[nj][1] - mn0);
            s[nj][2] = __expf(s[nj][2] - mn1);
            s[nj][3] = __expf(s[nj][3] - mn1);
            rs0 += s[nj][0] + s[nj][1];
            rs1 += s[nj][2] + s[nj][3];
        }
        rs0 += __shfl_xor_sync(0xffffffffu, rs0, 1);
        rs0 += __shfl_xor_sync(0xffffffffu, rs0, 2);
        rs1 += __shfl_xor_sync(0xffffffffu, rs1, 1);
        rs1 += __shfl_xor_sync(0xffffffffu, rs1, 2);
        l0r = l0r * a0 + rs0;
        l1r = l1r * a1 + rs1;

#pragma unroll
        for (int nj = 0; nj < 16; nj++) {
            o_acc[nj][0] *= a0; o_acc[nj][1] *= a0;
            o_acc[nj][2] *= a1; o_acc[nj][3] *= a1;
        }

        // ---- write P (exact hi/lo split) ----
#pragma unroll
        for (int nj = 0; nj < 8; nj++) {
            unsigned hi, lo;
            split2(s[nj][0], s[nj][1], hi, lo);
            Ph[(wq0 + grp) * VSTR + nj * 4 + qid] = hi;
            Pl[(wq0 + grp) * VSTR + nj * 4 + qid] = lo;
            split2(s[nj][2], s[nj][3], hi, lo);
            Ph[(wq0 + grp + 8) * VSTR + nj * 4 + qid] = hi;
            Pl[(wq0 + grp + 8) * VSTR + nj * 4 + qid] = lo;
        }
        __syncwarp();

        // ---- O += P V ----
#pragma unroll
        for (int kk = 0; kk < 4; kk++) {
            unsigned ah[4], al[4];
            const unsigned* p0 = Ph + (wq0 + grp) * VSTR + kk * 8 + qid;
            const unsigned* p1 = Ph + (wq0 + grp + 8) * VSTR + kk * 8 + qid;
            ah[0] = p0[0]; ah[1] = p1[0]; ah[2] = p0[4]; ah[3] = p1[4];
            const unsigned* q0p = Pl + (wq0 + grp) * VSTR + kk * 8 + qid;
            const unsigned* q1p = Pl + (wq0 + grp + 8) * VSTR + kk * 8 + qid;
            al[0] = q0p[0]; al[1] = q1p[0]; al[2] = q0p[4]; al[3] = q1p[4];
#pragma unroll
            for (int nj = 0; nj < 16; nj++) {
                const unsigned* bh = Vth + (nj * 8 + grp) * VSTR + kk * 8 + qid;
                const unsigned* bl = Vtl + (nj * 8 + grp) * VSTR + kk * 8 + qid;
                mma3(o_acc[nj], ah, al, bh[0], bh[4], bl[0], bl[4]);
            }
        }
    }

    // ---- epilogue: normalize + split-store ----
    const float il0 = 1.0f / l0r;
    const float il1 = 1.0f / l1r;
    const size_t r0 = (size_t)(b * S_ + q0 + wq0 + grp) * DP_;
    const size_t r1 = (size_t)(b * S_ + q0 + wq0 + grp + 8) * DP_;
#pragma unroll
    for (int nj = 0; nj < 16; nj++) {
        int col = h * 64 + nj * 4 + qid;
        unsigned hi, lo;
        split2(o_acc[nj][0] * il0, o_acc[nj][1] * il0, hi, lo);
        Oh[r0 + col] = hi; Ol[r0 + col] = lo;
        split2(o_acc[nj][2] * il1, o_acc[nj][3] * il1, hi, lo);
        Oh[r1 + col] = hi; Ol[r1 + col] = lo;
    }
}

// =====================================================================
// launch
// =====================================================================
extern "C" void kernel_launch(void* const* d_in, const int* in_sizes, int n_in,
                              void* d_out, int out_size)
{
    const float* x  = (const float*)d_in[0];
    const float* fc = (const float*)d_in[1];
    const float* fs = (const float*)d_in[2];
    const float* wq = (const float*)d_in[3];
    const float* wk = (const float*)d_in[4];
    const float* wv = (const float*)d_in[5];
    const float* wo = (const float*)d_in[6];
    float* out = (float*)d_out;

    float *q, *k, *v;
    unsigned *xh, *xl, *wqh, *wql, *wkh, *wkl, *wvh, *wvl, *woh, *wol, *ah, *al;
    cudaGetSymbolAddress((void**)&q,   g_q);
    cudaGetSymbolAddress((void**)&k,   g_k);
    cudaGetSymbolAddress((void**)&v,   g_v);
    cudaGetSymbolAddress((void**)&xh,  g_xh);  cudaGetSymbolAddress((void**)&xl,  g_xl);
    cudaGetSymbolAddress((void**)&wqh, g_wqh); cudaGetSymbolAddress((void**)&wql, g_wql);
    cudaGetSymbolAddress((void**)&wkh, g_wkh); cudaGetSymbolAddress((void**)&wkl, g_wkl);
    cudaGetSymbolAddress((void**)&wvh, g_wvh); cudaGetSymbolAddress((void**)&wvl, g_wvl);
    cudaGetSymbolAddress((void**)&woh, g_woh); cudaGetSymbolAddress((void**)&wol, g_wol);
    cudaGetSymbolAddress((void**)&ah,  g_ah);  cudaGetSymbolAddress((void**)&al,  g_al);

    // splits
    {
        int np;
        np = M_ * DP_;   split_kernel<<<np / 256, 256>>>(x,  xh,  xl,  np);
        np = D_ * DP_;   split_kernel<<<np / 256, 256>>>(wq, wqh, wql, np);
        np = KVD_ * DP_; split_kernel<<<np / 256, 256>>>(wk, wkh, wkl, np);
        np = KVD_ * DP_; split_kernel<<<np / 256, 256>>>(wv, wvh, wvl, np);
        np = D_ * DP_;   split_kernel<<<np / 256, 256>>>(wo, woh, wol, np);
    }

    const int GSMEM = 2 * 4 * GPL * 4;      // 81920 B
    cudaFuncSetAttribute(gemm3, cudaFuncAttributeMaxDynamicSharedMemorySize, GSMEM);

    // QKV projections
    gemm3<<<dim3(32, 32), 256, GSMEM>>>(xh, xl, wqh, wql, q, M_, D_,   D_);
    gemm3<<<dim3(8,  32), 256, GSMEM>>>(xh, xl, wkh, wkl, k, M_, KVD_, D_);
    gemm3<<<dim3(8,  32), 256, GSMEM>>>(xh, xl, wvh, wvl, v, M_, KVD_, D_);

    // RoPE
    {
        int tq = M_ * H_ * 64;
        rope_kernel<<<(tq + 255) / 256, 256>>>(q, fc, fs, 5, tq);
        int tk = M_ * HK_ * 64;
        rope_kernel<<<(tk + 255) / 256, 256>>>(k, fc, fs, 3, tk);
    }

    // attention
    {
        const int ASMEM = (2 * 64 * KSTR + 4 * 128 * VSTR) * 4;   // 108544 B
        cudaFuncSetAttribute(attn_mma, cudaFuncAttributeMaxDynamicSharedMemorySize, ASMEM);
        attn_mma<<<dim3(S_ / 128, H_, B_), 256, ASMEM>>>(q, k, v, ah, al);
    }

    // output projection
    gemm3<<<dim3(32, 32), 256, GSMEM>>>(ah, al, woh, wol, out, M_, D_, D_);
}